// round 5
// baseline (speedup 1.0000x reference)
#include <cuda_runtime.h>
#include <cstdint>

// Problem constants
#define B_    4096
#define LAT_  128
#define SEQ_  512
#define HID_  32
#define OUT_  64

#define WARPS_PER_BLOCK 8
#define THREADS (WARPS_PER_BLOCK * 32)

typedef unsigned long long ull;

__device__ __forceinline__ ull f2fma(ull a, ull b, ull c) {
    ull d;
    asm("fma.rn.f32x2 %0, %1, %2, %3;" : "=l"(d) : "l"(a), "l"(b), "l"(c));
    return d;
}
__device__ __forceinline__ ull f2pack(float lo, float hi) {
    ull r; asm("mov.b64 %0, {%1, %2};" : "=l"(r) : "f"(lo), "f"(hi)); return r;
}
__device__ __forceinline__ float f2sum(ull v) {
    float lo, hi; asm("mov.b64 {%0, %1}, %2;" : "=f"(lo), "=f"(hi) : "l"(v));
    return lo + hi;
}

// sigmoid / tanh via MUFU EX2 + RCP (proven 2.7e-7 end-to-end)
__device__ __forceinline__ float sigf(float x) {
    float e = __expf(-x);
    return __fdividef(1.0f, 1.0f + e);
}
__device__ __forceinline__ float tanhf_fast(float x) {
    float e = __expf(-2.0f * x);
    return __fdividef(2.0f, 1.0f + e) - 1.0f;
}

// 16-byte shared load: two f32x2 pairs at once (LDS.128)
__device__ __forceinline__ void lds128(ull& a, ull& b, const float* p) {
    asm volatile("ld.shared.v4.b32 {%0, %1, %2, %3}, [%4];"
                 : "=r"(*(uint32_t*)&a), "=r"(((uint32_t*)&a)[1]),
                   "=r"(*(uint32_t*)&b), "=r"(((uint32_t*)&b)[1])
                 : "l"(__cvta_generic_to_shared(p)));
}

__global__ void __launch_bounds__(THREADS, 1)
lstm_decoder_kernel(const float* __restrict__ z,
                    const float* __restrict__ init_W,
                    const float* __restrict__ init_b,
                    const float* __restrict__ W_hh,
                    const float* __restrict__ b_ih,
                    const float* __restrict__ b_hh,
                    const float* __restrict__ out_W,
                    const float* __restrict__ out_b,
                    float* __restrict__ y)
{
    __shared__ __align__(16) float whh_s[128 * 34];   // 17408 B (padded stage)
    __shared__ __align__(16) float outw_s[64 * 34];   //  8704 B
    __shared__ __align__(16) float iwT_s[128 * 32];   // 16384 B (transposed init_W)
    __shared__ __align__(16) float zs[WARPS_PER_BLOCK * 128];     // 4096 B
    __shared__ __align__(16) float hb[2][WARPS_PER_BLOCK * 32];   // 2048 B (double buffer)

    const int tid  = threadIdx.x;
    const int w    = tid >> 5;      // warp in block
    const int j    = tid & 31;      // lane
    const int b    = blockIdx.x * WARPS_PER_BLOCK + w;   // batch element

    // ---- stage weights into smem (coalesced global reads) ----
    for (int i = tid; i < 128 * 32; i += THREADS)
        whh_s[(i >> 5) * 34 + (i & 31)] = W_hh[i];
    for (int i = tid; i < 64 * 32; i += THREADS)
        outw_s[(i >> 5) * 34 + (i & 31)] = out_W[i];
    for (int i = tid; i < 32 * 128; i += THREADS) {
        int jj = i >> 7, kk = i & 127;
        iwT_s[kk * 32 + jj] = init_W[i];
    }
    for (int kk = j; kk < 128; kk += 32)
        zs[w * 128 + kk] = z[(size_t)b * LAT_ + kk];
    __syncthreads();

    // ---- per-lane weights into registers as f32x2 pairs (192 regs) ----
    // gates: W_hh rows j, 32+j, 64+j, 96+j ; projection: out_W rows 2j, 2j+1
    ull Wi[16], Wf[16], Wg[16], Wo[16], Pa[16], Pb[16];
#pragma unroll
    for (int m = 0; m < 16; m++) {
        Wi[m] = *reinterpret_cast<const ull*>(&whh_s[(j      ) * 34 + 2 * m]);
        Wf[m] = *reinterpret_cast<const ull*>(&whh_s[(32 + j ) * 34 + 2 * m]);
        Wg[m] = *reinterpret_cast<const ull*>(&whh_s[(64 + j ) * 34 + 2 * m]);
        Wo[m] = *reinterpret_cast<const ull*>(&whh_s[(96 + j ) * 34 + 2 * m]);
        Pa[m] = *reinterpret_cast<const ull*>(&outw_s[(2 * j    ) * 34 + 2 * m]);
        Pb[m] = *reinterpret_cast<const ull*>(&outw_s[(2 * j + 1) * 34 + 2 * m]);
    }

    // ---- h0 = z @ init_W^T + init_b ----
    float h = init_b[j];
#pragma unroll 8
    for (int k = 0; k < 128; k++)
        h = fmaf(zs[w * 128 + k], iwT_s[k * 32 + j], h);
    float c = 0.0f;

    const float bi  = b_ih[j]       + b_hh[j];
    const float bf  = b_ih[32 + j]  + b_hh[32 + j];
    const float bg  = b_ih[64 + j]  + b_hh[64 + j];
    const float bo  = b_ih[96 + j]  + b_hh[96 + j];
    const float ob0 = out_b[2 * j];
    const float ob1 = out_b[2 * j + 1];

    float* yo = y + (size_t)b * SEQ_ * OUT_;

#define GATE4(G0, HP0, HP1, HP2, HP3)                                   \
    do {                                                                \
        ai = f2fma(Wi[G0  ], HP0, ai); af = f2fma(Wf[G0  ], HP0, af);   \
        ag = f2fma(Wg[G0  ], HP0, ag); ao = f2fma(Wo[G0  ], HP0, ao);   \
        y0 = f2fma(Pa[G0  ], HP0, y0); y1 = f2fma(Pb[G0  ], HP0, y1);   \
        ai = f2fma(Wi[G0+1], HP1, ai); af = f2fma(Wf[G0+1], HP1, af);   \
        ag = f2fma(Wg[G0+1], HP1, ag); ao = f2fma(Wo[G0+1], HP1, ao);   \
        y0 = f2fma(Pa[G0+1], HP1, y0); y1 = f2fma(Pb[G0+1], HP1, y1);   \
        ai = f2fma(Wi[G0+2], HP2, ai); af = f2fma(Wf[G0+2], HP2, af);   \
        ag = f2fma(Wg[G0+2], HP2, ag); ao = f2fma(Wo[G0+2], HP2, ao);   \
        y0 = f2fma(Pa[G0+2], HP2, y0); y1 = f2fma(Pb[G0+2], HP2, y1);   \
        ai = f2fma(Wi[G0+3], HP3, ai); af = f2fma(Wf[G0+3], HP3, af);   \
        ag = f2fma(Wg[G0+3], HP3, ag); ao = f2fma(Wo[G0+3], HP3, ao);   \
        y0 = f2fma(Pa[G0+3], HP3, y0); y1 = f2fma(Pb[G0+3], HP3, y1);   \
    } while (0)

    // ---- main recurrence; projection of h_t fused; software-pipelined LDS ----
    for (int t = 0; t < SEQ_; t++) {
        float* hbw = &hb[t & 1][w * 32];
        hbw[j] = h;
        __syncwarp();

        ull ai = f2pack(bi, 0.0f), af = f2pack(bf, 0.0f);
        ull ag = f2pack(bg, 0.0f), ao = f2pack(bo, 0.0f);
        ull y0 = f2pack(ob0, 0.0f), y1 = f2pack(ob1, 0.0f);

        // prefetch group 0 (pairs 0..3) as two LDS.128
        ull a0, a1, a2, a3, b0, b1, b2, b3;
        lds128(a0, a1, &hbw[0]);
        lds128(a2, a3, &hbw[4]);
        // prefetch group 1 before consuming group 0
        lds128(b0, b1, &hbw[8]);
        lds128(b2, b3, &hbw[12]);
        GATE4(0, a0, a1, a2, a3);
        lds128(a0, a1, &hbw[16]);
        lds128(a2, a3, &hbw[20]);
        GATE4(4, b0, b1, b2, b3);
        lds128(b0, b1, &hbw[24]);
        lds128(b2, b3, &hbw[28]);
        GATE4(8, a0, a1, a2, a3);
        GATE4(12, b0, b1, b2, b3);

        if (t > 0) {   // y[t-1] = proj(h_t), one coalesced STG.64 per warp
            *reinterpret_cast<ull*>(yo + (t - 1) * OUT_ + 2 * j) =
                f2pack(f2sum(y0), f2sum(y1));
        }

        float gi = f2sum(ai), gf = f2sum(af), gg = f2sum(ag), go = f2sum(ao);
        float I = sigf(gi), F = sigf(gf), G = tanhf_fast(gg), O = sigf(go);
        c = fmaf(F, c, I * G);
        h = O * tanhf_fast(c);
        // next iteration writes the other hb buffer: one syncwarp per step
    }

    // ---- peeled final projection: y[511] = proj(h_512) ----
    {
        float* hbw = &hb[SEQ_ & 1][w * 32];
        hbw[j] = h;
        __syncwarp();
        ull y0 = f2pack(ob0, 0.0f), y1 = f2pack(ob1, 0.0f);
#pragma unroll
        for (int m = 0; m < 16; m++) {
            ull hp = *reinterpret_cast<const ull*>(&hbw[2 * m]);
            y0 = f2fma(Pa[m], hp, y0);
            y1 = f2fma(Pb[m], hp, y1);
        }
        *reinterpret_cast<ull*>(yo + (SEQ_ - 1) * OUT_ + 2 * j) =
            f2pack(f2sum(y0), f2sum(y1));
    }
#undef GATE4
}

extern "C" void kernel_launch(void* const* d_in, const int* in_sizes, int n_in,
                              void* d_out, int out_size)
{
    // metadata order: z, init_W, init_b, W_ih, W_hh, b_ih, b_hh, out_W, out_b
    const float* z      = (const float*)d_in[0];
    const float* init_W = (const float*)d_in[1];
    const float* init_b = (const float*)d_in[2];
    // d_in[3] = W_ih: unused (input sequence is all zeros)
    const float* W_hh   = (const float*)d_in[4];
    const float* b_ih   = (const float*)d_in[5];
    const float* b_hh   = (const float*)d_in[6];
    const float* out_W  = (const float*)d_in[7];
    const float* out_b  = (const float*)d_in[8];
    float* y            = (float*)d_out;

    dim3 grid(B_ / WARPS_PER_BLOCK);   // 512 blocks
    dim3 block(THREADS);               // 8 warps = 8 batch rows
    lstm_decoder_kernel<<<grid, block>>>(z, init_W, init_b, W_hh,
                                         b_ih, b_hh, out_W, out_b, y);
}

// round 6
// speedup vs baseline: 2.6297x; 2.6297x over previous
#include <cuda_runtime.h>
#include <cuda_fp16.h>
#include <cstdint>

#define B_    4096
#define LAT_  128
#define SEQ_  512
#define HID_  32
#define OUT_  64

#define ROWS_PER_CTA 32
#define NWARP 4
#define NTHREAD 128
#define ROWB 40   // h tile row stride in halves (80B = 5*16B, ldmatrix-aligned)

typedef uint32_t u32;

// exact-path activations (R1-proven: 2.7e-7 end-to-end in fp32)
__device__ __forceinline__ float sigf(float x) {
    float e = __expf(-x);
    return __fdividef(1.0f, 1.0f + e);
}
__device__ __forceinline__ float tanhf_fast(float x) {
    float e = __expf(-2.0f * x);
    return __fdividef(2.0f, 1.0f + e) - 1.0f;
}

__device__ __forceinline__ void ldsm4(u32 r[4], u32 saddr) {
    asm volatile("ldmatrix.sync.aligned.m8n8.x4.shared.b16 {%0,%1,%2,%3}, [%4];"
                 : "=r"(r[0]), "=r"(r[1]), "=r"(r[2]), "=r"(r[3])
                 : "r"(saddr));
}

// d = A*B + {c0,c1,c0,c1}
__device__ __forceinline__ void mma_init(float d[4], const u32 a[4], const u32 b[2],
                                         float c0, float c1) {
    asm volatile("mma.sync.aligned.m16n8k16.row.col.f32.f16.f16.f32 "
                 "{%0,%1,%2,%3}, {%4,%5,%6,%7}, {%8,%9}, {%10,%11,%12,%13};"
                 : "=f"(d[0]), "=f"(d[1]), "=f"(d[2]), "=f"(d[3])
                 : "r"(a[0]), "r"(a[1]), "r"(a[2]), "r"(a[3]),
                   "r"(b[0]), "r"(b[1]),
                   "f"(c0), "f"(c1), "f"(c0), "f"(c1));
}
// d += A*B
__device__ __forceinline__ void mma_acc(float d[4], const u32 a[4], const u32 b[2]) {
    asm volatile("mma.sync.aligned.m16n8k16.row.col.f32.f16.f16.f32 "
                 "{%0,%1,%2,%3}, {%4,%5,%6,%7}, {%8,%9}, {%0,%1,%2,%3};"
                 : "+f"(d[0]), "+f"(d[1]), "+f"(d[2]), "+f"(d[3])
                 : "r"(a[0]), "r"(a[1]), "r"(a[2]), "r"(a[3]),
                   "r"(b[0]), "r"(b[1]));
}

__device__ __forceinline__ u32 packh2(float lo, float hi) {
    __half2 p = __floats2half2_rn(lo, hi);
    return *reinterpret_cast<u32*>(&p);
}

__global__ void __launch_bounds__(NTHREAD, 1)
lstm_mma_kernel(const float* __restrict__ z,
                const float* __restrict__ init_W,
                const float* __restrict__ init_b,
                const float* __restrict__ W_hh,
                const float* __restrict__ b_ih,
                const float* __restrict__ b_hh,
                const float* __restrict__ out_W,
                const float* __restrict__ out_b,
                float* __restrict__ y)
{
    __shared__ __align__(16) __half hbuf[2][ROWS_PER_CTA][ROWB];   // 5120 B

    const int tid = threadIdx.x;
    const int w   = tid >> 5;          // warp 0..3
    const int l   = tid & 31;
    const int g   = l >> 2;            // groupID (fragment row)
    const int tig = l & 3;             // thread-in-group (fragment col pair)
    const int cta = blockIdx.x;

    // ---- static weight fragments (B operand, fp16), loaded once ----
    // gates: warp w covers H-cols [8w,8w+8) of each gate; B[k][n] = W_hh[n][k]
    u32 Bg[4][2][2];   // [gate][kstep][b0/b1]
#pragma unroll
    for (int G = 0; G < 4; G++) {
        const int row = G * 32 + 8 * w + g;          // W_hh row (gate col n)
#pragma unroll
        for (int s = 0; s < 2; s++)
#pragma unroll
            for (int hh = 0; hh < 2; hh++) {
                const int k = 2 * tig + 16 * s + 8 * hh;
                float2 v = *reinterpret_cast<const float2*>(W_hh + row * HID_ + k);
                Bg[G][s][hh] = packh2(v.x, v.y);
            }
    }
    // projection: warp w covers out-cols [8w,8w+8) and [32+8w,32+8w+8)
    u32 Bp[2][2][2];   // [ntile-i][kstep][b0/b1]
#pragma unroll
    for (int ti = 0; ti < 2; ti++) {
        const int row = (w + 4 * ti) * 8 + g;        // out_W row (out col n)
#pragma unroll
        for (int s = 0; s < 2; s++)
#pragma unroll
            for (int hh = 0; hh < 2; hh++) {
                const int k = 2 * tig + 16 * s + 8 * hh;
                float2 v = *reinterpret_cast<const float2*>(out_W + row * HID_ + k);
                Bp[ti][s][hh] = packh2(v.x, v.y);
            }
    }
    // biases (become HMMA C operands)
    float bg[4][2], pb[2][2];
#pragma unroll
    for (int G = 0; G < 4; G++) {
        const int n0 = G * 32 + 8 * w + 2 * tig;
        bg[G][0] = b_ih[n0]     + b_hh[n0];
        bg[G][1] = b_ih[n0 + 1] + b_hh[n0 + 1];
    }
#pragma unroll
    for (int ti = 0; ti < 2; ti++) {
        const int n0 = (w + 4 * ti) * 8 + 2 * tig;
        pb[ti][0] = out_b[n0];
        pb[ti][1] = out_b[n0 + 1];
    }

    // ---- h0 = z @ init_W^T + init_b  -> hbuf[0] (fp16) ----
    {
        const int row = tid >> 2;            // 0..31
        const int c0  = (tid & 3) * 8;       // 8 H-cols per thread
        float acc[8];
#pragma unroll
        for (int cc = 0; cc < 8; cc++) acc[cc] = init_b[c0 + cc];
        const float* zr = z + ((size_t)cta * ROWS_PER_CTA + row) * LAT_;
        for (int k = 0; k < LAT_; k++) {
            const float zk = zr[k];
#pragma unroll
            for (int cc = 0; cc < 8; cc++)
                acc[cc] = fmaf(zk, init_W[(c0 + cc) * LAT_ + k], acc[cc]);
        }
#pragma unroll
        for (int cc = 0; cc < 8; cc++)
            hbuf[0][row][c0 + cc] = __float2half(acc[cc]);
    }

    float cst[8];
#pragma unroll
    for (int i = 0; i < 8; i++) cst[i] = 0.0f;

    // shared-space addresses
    u32 hbase[2];
    hbase[0] = (u32)__cvta_generic_to_shared(&hbuf[0][0][0]);
    hbase[1] = (u32)__cvta_generic_to_shared(&hbuf[1][0][0]);
    const u32 off_ld = (u32)(((l & 15) * ROWB + (l >> 4) * 8) * 2);

    __syncthreads();

    // prime A fragments from h0
    u32 A[2][2][4];    // [Mtile][kstep][4]
#pragma unroll
    for (int m = 0; m < 2; m++)
#pragma unroll
        for (int s = 0; s < 2; s++)
            ldsm4(A[m][s], hbase[0] + off_ld + (u32)((m * 16 * ROWB + s * 16) * 2));

    // y base addresses per (Mtile): row = cta*32 + m*16 + g (and +8)
    const int ycol = 2 * tig;   // within the ntile; ntile col base added per-store
    float* ybase0 = y + ((size_t)cta * ROWS_PER_CTA + g) * (size_t)SEQ_ * OUT_;

#pragma unroll 1
    for (int t = 0; t < SEQ_; t++) {
        const int wb = (t + 1) & 1;          // write buffer this step

        // ---- gates = h_t @ W_hh^T + bias ----
        float dg[2][4][4];
#pragma unroll
        for (int m = 0; m < 2; m++)
#pragma unroll
            for (int G = 0; G < 4; G++) {
                mma_init(dg[m][G], A[m][0], Bg[G][0], bg[G][0], bg[G][1]);
                mma_acc (dg[m][G], A[m][1], Bg[G][1]);
            }

        // ---- nonlinearities: 8 cells/lane, c in registers ----
        float hv[2][2][2];
#pragma unroll
        for (int m = 0; m < 2; m++)
#pragma unroll
            for (int rr = 0; rr < 2; rr++)
#pragma unroll
                for (int cc = 0; cc < 2; cc++) {
                    const int di = rr * 2 + cc;
                    const int ci = m * 4 + rr * 2 + cc;
                    float I = sigf(dg[m][0][di]);
                    float F = sigf(dg[m][1][di]);
                    float G_ = tanhf_fast(dg[m][2][di]);
                    float O = sigf(dg[m][3][di]);
                    cst[ci] = fmaf(F, cst[ci], I * G_);
                    hv[m][rr][cc] = O * tanhf_fast(cst[ci]);
                }

        // ---- publish h_{t+1} (fp16) ----
#pragma unroll
        for (int m = 0; m < 2; m++)
#pragma unroll
            for (int rr = 0; rr < 2; rr++) {
                __half2 p = __floats2half2_rn(hv[m][rr][0], hv[m][rr][1]);
                *reinterpret_cast<__half2*>(
                    &hbuf[wb][m * 16 + g + rr * 8][8 * w + 2 * tig]) = p;
            }
        __syncthreads();

        // ---- reload A from h_{t+1}: serves proj(t) AND gates(t+1) ----
#pragma unroll
        for (int m = 0; m < 2; m++)
#pragma unroll
            for (int s = 0; s < 2; s++)
                ldsm4(A[m][s], hbase[wb] + off_ld + (u32)((m * 16 * ROWB + s * 16) * 2));

        // ---- y_t = h_{t+1} @ out_W^T + out_b ----
        float dp[2][2][4];
#pragma unroll
        for (int m = 0; m < 2; m++)
#pragma unroll
            for (int ti = 0; ti < 2; ti++) {
                mma_init(dp[m][ti], A[m][0], Bp[ti][0], pb[ti][0], pb[ti][1]);
                mma_acc (dp[m][ti], A[m][1], Bp[ti][1]);
            }

        // ---- store y fragments: 8x STG.64, sector-full ----
#pragma unroll
        for (int m = 0; m < 2; m++)
#pragma unroll
            for (int ti = 0; ti < 2; ti++) {
                const int col = (w + 4 * ti) * 8 + ycol;
                float* yr0 = ybase0 + (size_t)(m * 16) * SEQ_ * OUT_
                                    + (size_t)t * OUT_ + col;
                float* yr1 = yr0 + (size_t)8 * SEQ_ * OUT_;
                *reinterpret_cast<float2*>(yr0) = make_float2(dp[m][ti][0], dp[m][ti][1]);
                *reinterpret_cast<float2*>(yr1) = make_float2(dp[m][ti][2], dp[m][ti][3]);
            }
    }
}

extern "C" void kernel_launch(void* const* d_in, const int* in_sizes, int n_in,
                              void* d_out, int out_size)
{
    // metadata order: z, init_W, init_b, W_ih, W_hh, b_ih, b_hh, out_W, out_b
    const float* z      = (const float*)d_in[0];
    const float* init_W = (const float*)d_in[1];
    const float* init_b = (const float*)d_in[2];
    // d_in[3] = W_ih: unused (input sequence is all zeros)
    const float* W_hh   = (const float*)d_in[4];
    const float* b_ih   = (const float*)d_in[5];
    const float* b_hh   = (const float*)d_in[6];
    const float* out_W  = (const float*)d_in[7];
    const float* out_b  = (const float*)d_in[8];
    float* y            = (float*)d_out;

    lstm_mma_kernel<<<B_ / ROWS_PER_CTA, NTHREAD>>>(   // 128 CTAs x 128 thr
        z, init_W, init_b, W_hh, b_ih, b_hh, out_W, out_b, y);
}

// round 7
// speedup vs baseline: 5.1158x; 1.9454x over previous
#include <cuda_runtime.h>
#include <cuda_fp16.h>
#include <cstdint>

#define B_    4096
#define LAT_  128
#define SEQ_  512
#define HID_  32
#define OUT_  64

#define ROWS_PER_CTA 32
#define NTHREAD 256
#define ROWB 40   // h tile row stride in halves (80B, ldmatrix-friendly)

typedef uint32_t u32;

__device__ __forceinline__ float tanha(float x) {
    float r; asm("tanh.approx.f32 %0, %1;" : "=f"(r) : "f"(x)); return r;
}

__device__ __forceinline__ void ldsm4(u32 r[4], u32 saddr) {
    asm volatile("ldmatrix.sync.aligned.m8n8.x4.shared.b16 {%0,%1,%2,%3}, [%4];"
                 : "=r"(r[0]), "=r"(r[1]), "=r"(r[2]), "=r"(r[3])
                 : "r"(saddr));
}
__device__ __forceinline__ void mma_init(float d[4], const u32 a[4], const u32 b[2],
                                         float c0, float c1) {
    asm volatile("mma.sync.aligned.m16n8k16.row.col.f32.f16.f16.f32 "
                 "{%0,%1,%2,%3}, {%4,%5,%6,%7}, {%8,%9}, {%10,%11,%12,%13};"
                 : "=f"(d[0]), "=f"(d[1]), "=f"(d[2]), "=f"(d[3])
                 : "r"(a[0]), "r"(a[1]), "r"(a[2]), "r"(a[3]),
                   "r"(b[0]), "r"(b[1]),
                   "f"(c0), "f"(c1), "f"(c0), "f"(c1));
}
__device__ __forceinline__ void mma_acc(float d[4], const u32 a[4], const u32 b[2]) {
    asm volatile("mma.sync.aligned.m16n8k16.row.col.f32.f16.f16.f32 "
                 "{%0,%1,%2,%3}, {%4,%5,%6,%7}, {%8,%9}, {%0,%1,%2,%3};"
                 : "+f"(d[0]), "+f"(d[1]), "+f"(d[2]), "+f"(d[3])
                 : "r"(a[0]), "r"(a[1]), "r"(a[2]), "r"(a[3]),
                   "r"(b[0]), "r"(b[1]));
}
__device__ __forceinline__ u32 packh2(float lo, float hi) {
    __half2 p = __floats2half2_rn(lo, hi);
    return *reinterpret_cast<u32*>(&p);
}
#define GBAR(id) asm volatile("bar.sync %0, 128;" :: "r"(id) : "memory")

__global__ void __launch_bounds__(NTHREAD, 1)
lstm_mma_kernel(const float* __restrict__ z,
                const float* __restrict__ init_W,
                const float* __restrict__ init_b,
                const float* __restrict__ W_hh,
                const float* __restrict__ b_ih,
                const float* __restrict__ b_hh,
                const float* __restrict__ out_W,
                const float* __restrict__ out_b,
                float* __restrict__ y)
{
    __shared__ __align__(16) __half hbuf[2][ROWS_PER_CTA][ROWB];   // 5120 B

    const int tid = threadIdx.x;
    const int w   = tid >> 5;
    const int l   = tid & 31;
    const int g   = l >> 2;
    const int tig = l & 3;
    const int gid = w >> 2;            // row-group: 0 -> rows 0-15, 1 -> 16-31
    const int wg  = w & 3;             // warp within group: H-col slice
    const int cta = blockIdx.x;

    // ---- static weight fragments (fp16 B operands) ----
    // gates: warp wg covers H-cols [8wg, 8wg+8) of each gate
    // i/f/o gates pre-scaled by 0.5 so sigmoid(x) = 0.5*tanh(arg)+0.5 directly
    u32 Bg[4][2][2];
    float bg[4][2];
#pragma unroll
    for (int G = 0; G < 4; G++) {
        const float sc = (G == 2) ? 1.0f : 0.5f;
        const int row = G * 32 + 8 * wg + g;
#pragma unroll
        for (int s = 0; s < 2; s++)
#pragma unroll
            for (int hh = 0; hh < 2; hh++) {
                const int k = 2 * tig + 16 * s + 8 * hh;
                float2 v = *reinterpret_cast<const float2*>(W_hh + row * HID_ + k);
                Bg[G][s][hh] = packh2(v.x * sc, v.y * sc);
            }
        const int n0 = G * 32 + 8 * wg + 2 * tig;
        bg[G][0] = (b_ih[n0]     + b_hh[n0])     * sc;
        bg[G][1] = (b_ih[n0 + 1] + b_hh[n0 + 1]) * sc;
    }
    // projection: warp wg covers out-cols [8wg,8wg+8) and [32+8wg, ...)
    u32 Bp[2][2][2];
    float pb[2][2];
#pragma unroll
    for (int ti = 0; ti < 2; ti++) {
        const int row = (wg + 4 * ti) * 8 + g;
#pragma unroll
        for (int s = 0; s < 2; s++)
#pragma unroll
            for (int hh = 0; hh < 2; hh++) {
                const int k = 2 * tig + 16 * s + 8 * hh;
                float2 v = *reinterpret_cast<const float2*>(out_W + row * HID_ + k);
                Bp[ti][s][hh] = packh2(v.x, v.y);
            }
        const int n0 = (wg + 4 * ti) * 8 + 2 * tig;
        pb[ti][0] = out_b[n0];
        pb[ti][1] = out_b[n0 + 1];
    }

    // ---- h0 = z @ init_W^T + init_b -> hbuf[0] (fp16); group-local rows ----
    {
        const int row = tid >> 3;            // 0..31 (tid<128 -> rows 0..15)
        const int c0  = (tid & 7) * 4;       // 4 H-cols per thread
        float acc[4];
#pragma unroll
        for (int cc = 0; cc < 4; cc++) acc[cc] = init_b[c0 + cc];
        const float* zr = z + ((size_t)cta * ROWS_PER_CTA + row) * LAT_;
        for (int k = 0; k < LAT_; k++) {
            const float zk = zr[k];
#pragma unroll
            for (int cc = 0; cc < 4; cc++)
                acc[cc] = fmaf(zk, init_W[(c0 + cc) * LAT_ + k], acc[cc]);
        }
#pragma unroll
        for (int cc = 0; cc < 4; cc++)
            hbuf[0][row][c0 + cc] = __float2half(acc[cc]);
    }

    float cst[4];
#pragma unroll
    for (int i = 0; i < 4; i++) cst[i] = 0.0f;

    u32 hbase[2];
    hbase[0] = (u32)__cvta_generic_to_shared(&hbuf[0][0][0]);
    hbase[1] = (u32)__cvta_generic_to_shared(&hbuf[1][0][0]);
    const u32 grp_off = (u32)(gid * 16 * ROWB * 2);
    const u32 off_ld  = (u32)(((l & 15) * ROWB + (l >> 4) * 8) * 2);

    GBAR(1 + gid);

    // prime A fragments from h0 (this group's 16 rows)
    u32 A[2][4];
#pragma unroll
    for (int s = 0; s < 2; s++)
        ldsm4(A[s], hbase[0] + grp_off + off_ld + (u32)(s * 32));

    float* ybase0 = y + ((size_t)cta * ROWS_PER_CTA + gid * 16 + g)
                        * (size_t)SEQ_ * OUT_;

#pragma unroll 1
    for (int t = 0; t < SEQ_; t++) {
        const int wb = (t + 1) & 1;

        // ---- gates = h_t @ W_hh^T + bias (i/f/o pre-scaled 0.5) ----
        float dg[4][4];
#pragma unroll
        for (int G = 0; G < 4; G++) {
            mma_init(dg[G], A[0], Bg[G][0], bg[G][0], bg[G][1]);
            mma_acc (dg[G], A[1], Bg[G][1]);
        }

        // ---- nonlinearities: 4 cells/lane, 5 MUFU.TANH each ----
        float hv[2][2];
#pragma unroll
        for (int rr = 0; rr < 2; rr++)
#pragma unroll
            for (int cc = 0; cc < 2; cc++) {
                const int di = rr * 2 + cc;
                const int ci = rr * 2 + cc;
                float I = fmaf(tanha(dg[0][di]), 0.5f, 0.5f);
                float F = fmaf(tanha(dg[1][di]), 0.5f, 0.5f);
                float G_ = tanha(dg[2][di]);
                float O = fmaf(tanha(dg[3][di]), 0.5f, 0.5f);
                cst[ci] = fmaf(F, cst[ci], I * G_);
                hv[rr][cc] = O * tanha(cst[ci]);
            }

        // ---- publish h_{t+1} (fp16) ----
#pragma unroll
        for (int rr = 0; rr < 2; rr++)
            *reinterpret_cast<__half2*>(
                &hbuf[wb][gid * 16 + g + rr * 8][8 * wg + 2 * tig]) =
                __floats2half2_rn(hv[rr][0], hv[rr][1]);
        GBAR(1 + gid);

        // ---- reload A: serves proj(t) AND gates(t+1) ----
#pragma unroll
        for (int s = 0; s < 2; s++)
            ldsm4(A[s], hbase[wb] + grp_off + off_ld + (u32)(s * 32));

        // ---- y_t = h_{t+1} @ out_W^T + out_b ----
        float dp[2][4];
#pragma unroll
        for (int ti = 0; ti < 2; ti++) {
            mma_init(dp[ti], A[0], Bp[ti][0], pb[ti][0], pb[ti][1]);
            mma_acc (dp[ti], A[1], Bp[ti][1]);
        }
#pragma unroll
        for (int ti = 0; ti < 2; ti++) {
            const int col = (wg + 4 * ti) * 8 + 2 * tig;
            float* yr0 = ybase0 + (size_t)t * OUT_ + col;
            float* yr1 = yr0 + (size_t)8 * SEQ_ * OUT_;
            *reinterpret_cast<float2*>(yr0) = make_float2(dp[ti][0], dp[ti][1]);
            *reinterpret_cast<float2*>(yr1) = make_float2(dp[ti][2], dp[ti][3]);
        }
    }
}

extern "C" void kernel_launch(void* const* d_in, const int* in_sizes, int n_in,
                              void* d_out, int out_size)
{
    // metadata order: z, init_W, init_b, W_ih, W_hh, b_ih, b_hh, out_W, out_b
    const float* z      = (const float*)d_in[0];
    const float* init_W = (const float*)d_in[1];
    const float* init_b = (const float*)d_in[2];
    // d_in[3] = W_ih: unused (input sequence is all zeros)
    const float* W_hh   = (const float*)d_in[4];
    const float* b_ih   = (const float*)d_in[5];
    const float* b_hh   = (const float*)d_in[6];
    const float* out_W  = (const float*)d_in[7];
    const float* out_b  = (const float*)d_in[8];
    float* y            = (float*)d_out;

    lstm_mma_kernel<<<B_ / ROWS_PER_CTA, NTHREAD>>>(   // 128 CTAs x 256 thr
        z, init_W, init_b, W_hh, b_ih, b_hh, out_W, out_b, y);
}